// round 1
// baseline (speedup 1.0000x reference)
#include <cuda_runtime.h>
#include <cstdint>
#include <cstdio>

#define EPS   1e-5f
#define NB    512
#define NP    512
#define M_TOT (NB*NP)   // 262144 points

// ---------------- scratch (device globals: no allocation allowed) ----------
__device__ float g_h [(size_t)M_TOT * 128];   // raw x@W1+b1
__device__ float g_y [(size_t)M_TOT * 256];   // masked first-mlp output
__device__ float g_h2[(size_t)M_TOT * 256];   // raw feat@W3+b3
__device__ float g_pooled[NB * 256];
__device__ float g_pb    [NB * 256];          // pooled@W3_bot + b3 (per-batch row bias)
__device__ float g_sum1[128], g_ss1[128];
__device__ float g_sum2[256], g_ss2[256];
__device__ float g_cnt;
__device__ float g_scale1[128], g_shift1[128];
__device__ float g_scale2[256], g_shift2[256];

// ---------------- init: zero out + stats accumulators ----------------------
__global__ void k_init(float* __restrict__ out) {
    int i = blockIdx.x * blockDim.x + threadIdx.x;
    if (i < 65536) out[i] = 0.f;          // out = max(..., zeros participate) -> init 0
    if (i < 128) { g_sum1[i] = 0.f; g_ss1[i] = 0.f; }
    if (i < 256) { g_sum2[i] = 0.f; g_ss2[i] = 0.f; }
    if (i == 0)  g_cnt = 0.f;
}

// ---------------- K1: h = x@W1 + b1 (store raw) + masked stats -------------
__global__ void k_h_stats(const float* __restrict__ x, const int* __restrict__ mask,
                          const float* __restrict__ W1, const float* __restrict__ b1) {
    int c  = threadIdx.x;            // channel 0..127
    int p0 = blockIdx.x * 128;       // 128 points per block
    __shared__ float xs[128 * 6];
    __shared__ int   ms[128];
    for (int idx = c; idx < 768; idx += 128) xs[idx] = x[p0 * 6 + idx];
    ms[c] = mask[p0 + c];
    __syncthreads();

    float w0 = W1[0*128+c], w1 = W1[1*128+c], w2 = W1[2*128+c];
    float w3 = W1[3*128+c], w4 = W1[4*128+c], w5 = W1[5*128+c];
    float bb = b1[c];
    float s = 0.f, ss = 0.f; int cnt = 0;
    for (int i = 0; i < 128; i++) {
        const float* xp = &xs[i * 6];
        float t = bb + xp[0]*w0 + xp[1]*w1 + xp[2]*w2 + xp[3]*w3 + xp[4]*w4 + xp[5]*w5;
        g_h[(size_t)(p0 + i) * 128 + c] = t;
        if (ms[i]) { s += t; ss += t * t; cnt++; }
    }
    atomicAdd(&g_sum1[c], s);
    atomicAdd(&g_ss1[c],  ss);
    if (c == 0) atomicAdd(&g_cnt, (float)cnt);
}

// ---------------- BN finalize: fold gamma/beta into scale/shift ------------
__global__ void k_fin1(const float* __restrict__ g1, const float* __restrict__ be1) {
    int c = threadIdx.x;
    float cnt  = g_cnt;
    float mean = g_sum1[c] / cnt;
    float var  = g_ss1[c] / cnt - mean * mean;
    float sc   = g1[c] * rsqrtf(var + EPS);
    g_scale1[c] = sc;
    g_shift1[c] = be1[c] - mean * sc;
}
__global__ void k_fin2(const float* __restrict__ g2, const float* __restrict__ be2) {
    int c = threadIdx.x;
    float cnt  = g_cnt;
    float mean = g_sum2[c] / cnt;
    float var  = g_ss2[c] / cnt - mean * mean;
    float sc   = g2[c] * rsqrtf(var + EPS);
    g_scale2[c] = sc;
    g_shift2[c] = be2[c] - mean * sc;
}

// ---------------- tiled SGEMM, 128x64 tile, BK=16, 256 thr, 8x4 micro-tile -
// AMODE: 0 = plain A load, 1 = apply relu(A*scale[k]+shift[k]) on load
// EMODE: 0 = +bias[col], *mask[row], store C
//        1 = +bias[batch*256+col] (pb), store C
//        2 = +bias[col], *mask[row], block max over rows, atomicMax -> C[batch*NTOT+col]
template<int KTOT, int NTOT, int AMODE, int EMODE>
__global__ void __launch_bounds__(256, 2) k_gemm(
    const float* __restrict__ A, const float* __restrict__ Bm,
    const float* __restrict__ bias, const int* __restrict__ mask,
    const float* __restrict__ scA, const float* __restrict__ shA,
    float* __restrict__ C)
{
    __shared__ float As[16][132];   // [k][m], padded (132*4 % 16 == 0 keeps float4 align)
    __shared__ float Bs[16][64];    // [k][n]

    int tid = threadIdx.x;
    int tx = tid & 15, ty = tid >> 4;        // 16 x 16
    int rowBase = blockIdx.y * 128;
    int colBase = blockIdx.x * 64;
    int aRow = tid >> 1;                      // 0..127
    int aK8  = (tid & 1) * 8;                 // 0 or 8
    int bK   = tid >> 4;                      // 0..15
    int bN4  = (tid & 15) * 4;

    float acc[8][4];
#pragma unroll
    for (int i = 0; i < 8; i++)
#pragma unroll
        for (int j = 0; j < 4; j++) acc[i][j] = 0.f;

    const float* Ap = A + (size_t)(rowBase + aRow) * KTOT + aK8;

    for (int k0 = 0; k0 < KTOT; k0 += 16) {
        float4 a0 = *(const float4*)(Ap + k0);
        float4 a1 = *(const float4*)(Ap + k0 + 4);
        if (AMODE == 1) {
            float4 s0 = *(const float4*)&scA[k0 + aK8];
            float4 s1 = *(const float4*)&scA[k0 + aK8 + 4];
            float4 h0 = *(const float4*)&shA[k0 + aK8];
            float4 h1 = *(const float4*)&shA[k0 + aK8 + 4];
            a0.x = fmaxf(a0.x*s0.x + h0.x, 0.f); a0.y = fmaxf(a0.y*s0.y + h0.y, 0.f);
            a0.z = fmaxf(a0.z*s0.z + h0.z, 0.f); a0.w = fmaxf(a0.w*s0.w + h0.w, 0.f);
            a1.x = fmaxf(a1.x*s1.x + h1.x, 0.f); a1.y = fmaxf(a1.y*s1.y + h1.y, 0.f);
            a1.z = fmaxf(a1.z*s1.z + h1.z, 0.f); a1.w = fmaxf(a1.w*s1.w + h1.w, 0.f);
        }
        As[aK8+0][aRow] = a0.x; As[aK8+1][aRow] = a0.y;
        As[aK8+2][aRow] = a0.z; As[aK8+3][aRow] = a0.w;
        As[aK8+4][aRow] = a1.x; As[aK8+5][aRow] = a1.y;
        As[aK8+6][aRow] = a1.z; As[aK8+7][aRow] = a1.w;
        *(float4*)&Bs[bK][bN4] = *(const float4*)&Bm[(size_t)(k0 + bK) * NTOT + colBase + bN4];
        __syncthreads();

#pragma unroll
        for (int k = 0; k < 16; k++) {
            float4 av0 = *(const float4*)&As[k][ty * 8];
            float4 av1 = *(const float4*)&As[k][ty * 8 + 4];
            float4 bv  = *(const float4*)&Bs[k][tx * 4];
            float a_[8] = {av0.x, av0.y, av0.z, av0.w, av1.x, av1.y, av1.z, av1.w};
            float b_[4] = {bv.x, bv.y, bv.z, bv.w};
#pragma unroll
            for (int i = 0; i < 8; i++)
#pragma unroll
                for (int j = 0; j < 4; j++)
                    acc[i][j] += a_[i] * b_[j];
        }
        __syncthreads();
    }

    int batch = rowBase >> 9;   // 128 | 512, tile is within one batch

    if (EMODE == 0 || EMODE == 1) {
        float4 bias4;
        if (EMODE == 0) bias4 = *(const float4*)&bias[colBase + tx * 4];
        else            bias4 = *(const float4*)&bias[batch * 256 + colBase + tx * 4];
#pragma unroll
        for (int i = 0; i < 8; i++) {
            int r = rowBase + ty * 8 + i;
            float mf = 1.f;
            if (EMODE == 0) mf = (mask[r] != 0) ? 1.f : 0.f;
            float4 o;
            o.x = (acc[i][0] + bias4.x) * mf;
            o.y = (acc[i][1] + bias4.y) * mf;
            o.z = (acc[i][2] + bias4.z) * mf;
            o.w = (acc[i][3] + bias4.w) * mf;
            *(float4*)&C[(size_t)r * NTOT + colBase + tx * 4] = o;
        }
    } else {
        float4 bias4 = *(const float4*)&bias[colBase + tx * 4];
        // masked rows contribute exact 0; out is zero-initialized, so 0-init max is exact
        float cm[4] = {0.f, 0.f, 0.f, 0.f};
#pragma unroll
        for (int i = 0; i < 8; i++) {
            int r = rowBase + ty * 8 + i;
            float mf = (mask[r] != 0) ? 1.f : 0.f;
            cm[0] = fmaxf(cm[0], (acc[i][0] + bias4.x) * mf);
            cm[1] = fmaxf(cm[1], (acc[i][1] + bias4.y) * mf);
            cm[2] = fmaxf(cm[2], (acc[i][2] + bias4.z) * mf);
            cm[3] = fmaxf(cm[3], (acc[i][3] + bias4.w) * mf);
        }
        // reuse As as [16][64] scratch (mainloop finished, all threads past sync)
        As[ty][tx * 4 + 0] = cm[0];
        As[ty][tx * 4 + 1] = cm[1];
        As[ty][tx * 4 + 2] = cm[2];
        As[ty][tx * 4 + 3] = cm[3];
        __syncthreads();
        if (tid < 64) {
            float m = As[0][tid];
#pragma unroll
            for (int t = 1; t < 16; t++) m = fmaxf(m, As[t][tid]);
            // positive-only atomicMax: int compare == float compare for m > 0
            if (m > 0.f)
                atomicMax((int*)&C[batch * NTOT + colBase + tid], __float_as_int(m));
        }
    }
}

// ---------------- max-pool over N: pooled[b,j] = max_n g_y ------------------
__global__ void k_pool() {
    int b = blockIdx.x, j = threadIdx.x;  // 512 x 256
    const float* yp = g_y + (size_t)b * NP * 256 + j;
    float m = -3.402823466e+38f;
#pragma unroll 8
    for (int n = 0; n < NP; n++) m = fmaxf(m, yp[(size_t)n * 256]);
    g_pooled[b * 256 + j] = m;
}

// ---------------- pb[b,j] = b3[j] + pooled[b,:] @ W3[256:,:] ----------------
__global__ void k_pb(const float* __restrict__ W3, const float* __restrict__ b3) {
    int b = blockIdx.x, j = threadIdx.x;   // 512 x 256
    __shared__ float pl[256];
    pl[j] = g_pooled[b * 256 + j];
    __syncthreads();
    float s = b3[j];
#pragma unroll 4
    for (int k = 0; k < 256; k++) s += pl[k] * W3[(256 + k) * 256 + j];
    g_pb[b * 256 + j] = s;
}

// ---------------- stats over raw h2 (masked) --------------------------------
__global__ void k_stats2(const int* __restrict__ mask) {
    int c  = threadIdx.x;          // 0..255
    int p0 = blockIdx.x * 128;
    __shared__ int ms[128];
    if (c < 128) ms[c] = mask[p0 + c];
    __syncthreads();
    float s = 0.f, ss = 0.f;
    for (int i = 0; i < 128; i++) {
        if (ms[i]) {
            float v = g_h2[(size_t)(p0 + i) * 256 + c];
            s += v; ss += v * v;
        }
    }
    atomicAdd(&g_sum2[c], s);
    atomicAdd(&g_ss2[c],  ss);
}

// ---------------- launch ----------------------------------------------------
extern "C" void kernel_launch(void* const* d_in, const int* in_sizes, int n_in,
                              void* d_out, int out_size) {
    const float* x   = (const float*)d_in[0];
    const int*   mask= (const int*)  d_in[1];
    const float* W1  = (const float*)d_in[2];
    const float* b1  = (const float*)d_in[3];
    const float* g1  = (const float*)d_in[4];
    const float* be1 = (const float*)d_in[5];
    const float* W2  = (const float*)d_in[6];
    const float* b2  = (const float*)d_in[7];
    const float* W3  = (const float*)d_in[8];
    const float* b3  = (const float*)d_in[9];
    const float* g2  = (const float*)d_in[10];
    const float* be2 = (const float*)d_in[11];
    const float* W4  = (const float*)d_in[12];
    const float* b4  = (const float*)d_in[13];
    float* out = (float*)d_out;

    float *p_h, *p_y, *p_h2, *p_pb, *p_sc1, *p_sh1, *p_sc2, *p_sh2;
    cudaGetSymbolAddress((void**)&p_h,   g_h);
    cudaGetSymbolAddress((void**)&p_y,   g_y);
    cudaGetSymbolAddress((void**)&p_h2,  g_h2);
    cudaGetSymbolAddress((void**)&p_pb,  g_pb);
    cudaGetSymbolAddress((void**)&p_sc1, g_scale1);
    cudaGetSymbolAddress((void**)&p_sh1, g_shift1);
    cudaGetSymbolAddress((void**)&p_sc2, g_scale2);
    cudaGetSymbolAddress((void**)&p_sh2, g_shift2);

    k_init   <<<256, 256>>>(out);
    k_h_stats<<<2048, 128>>>(x, mask, W1, b1);
    k_fin1   <<<1, 128>>>(g1, be1);
    // GEMM2: y = (relu(bn1(g_h)) @ W2 + b2) * mask
    k_gemm<128, 256, 1, 0><<<dim3(4, 2048), 256>>>(p_h, W2, b2, mask, p_sc1, p_sh1, p_y);
    k_pool   <<<512, 256>>>();
    k_pb     <<<512, 256>>>(W3, b3);
    // GEMM3: h2 = y @ W3[:256,:] + pb[batch]
    k_gemm<256, 256, 0, 1><<<dim3(4, 2048), 256>>>(p_y, W3, p_pb, mask, nullptr, nullptr, p_h2);
    k_stats2 <<<2048, 256>>>(mask);
    k_fin2   <<<1, 256>>>(g2, be2);
    // GEMM4: out = max_n ((relu(bn2(h2)) @ W4 + b4) * mask)
    k_gemm<256, 128, 1, 2><<<dim3(2, 2048), 256>>>(p_h2, W4, b4, mask, p_sc2, p_sh2, out);
}